// round 1
// baseline (speedup 1.0000x reference)
#include <cuda_runtime.h>
#include <math.h>

// Problem constants
#define EMBED   256
#define NHEADS  4
#define HDIM    64
#define BATCHB  4
#define SEQ     2048
#define ROWS    (BATCHB*SEQ)          // 8192 rows per stream
#define BH      (BATCHB*NHEADS)       // 16 batched attention slices
#define NNL     ((long)SEQ*(long)SEQ) // 4,194,304 logits per slice

// ---------------- scratch (static device globals; no allocation) -----------
__device__ float g_qk0[ROWS*EMBED];
__device__ float g_qk1[ROWS*EMBED];
__device__ float g_v0 [ROWS*EMBED];
__device__ float g_v1 [ROWS*EMBED];
__device__ float g_S  [(long)BH*SEQ*SEQ];   // 256 MB logits buffer (reused per direction)
__device__ float g_m0 [ROWS*EMBED];
__device__ float g_m1 [ROWS*EMBED];
__device__ float g_mo [ROWS*EMBED];
__device__ float g_cat[ROWS*2*EMBED];
__device__ float g_y  [ROWS*2*EMBED];

// ---------------- generic tiled fp32 GEMM ----------------------------------
// C[z] = alpha * A[z] @ op(B[z]) (+bias) (+resid)
// Batch offset per z: (z/H)*outer + (z%H)*inner  for each of A,B,C
// (lets head-sliced tensors [B,N,D] with head column offset h*64 batch cleanly)
template<int BM, int BN, int TM, int TN, int TRANSB>
__global__ void gemm_kernel(
    const float* __restrict__ A, const float* __restrict__ B,
    const float* __restrict__ bias, const float* __restrict__ resid,
    float* __restrict__ C,
    int M, int N, int K, int lda, int ldb, int ldc, int ldr,
    long aOuter, long aInner, long bOuter, long bInner, long cOuter, long cInner,
    int H, float alpha)
{
    constexpr int BK = 16;
    constexpr int NT = 256;
    constexpr int TX = BN / TN;   // threads along N

    __shared__ float As[BK][BM + 4];
    __shared__ float Bs[BK][BN + 4];

    int z  = blockIdx.z;
    int zo = z / H, zi = z % H;
    A += (long)zo * aOuter + (long)zi * aInner;
    B += (long)zo * bOuter + (long)zi * bInner;
    C += (long)zo * cOuter + (long)zi * cInner;

    int tid = threadIdx.x;
    int tx = tid % TX, ty = tid / TX;
    int rowBase = blockIdx.y * BM;
    int colBase = blockIdx.x * BN;

    float acc[TM][TN];
    #pragma unroll
    for (int i = 0; i < TM; i++)
        #pragma unroll
        for (int j = 0; j < TN; j++) acc[i][j] = 0.f;

    for (int k0 = 0; k0 < K; k0 += BK) {
        // load A tile (BM x BK): consecutive tid -> consecutive k (coalesced 64B)
        #pragma unroll
        for (int i = tid; i < BM * BK; i += NT) {
            int m = i / BK, k = i % BK;
            int gm = rowBase + m;
            As[k][m] = (gm < M) ? A[(long)gm * lda + (k0 + k)] : 0.f;
        }
        // load B tile (BK x BN)
        if (TRANSB) {
            #pragma unroll
            for (int i = tid; i < BN * BK; i += NT) {
                int n = i / BK, k = i % BK;
                int gn = colBase + n;
                Bs[k][n] = (gn < N) ? B[(long)gn * ldb + (k0 + k)] : 0.f;
            }
        } else {
            #pragma unroll
            for (int i = tid; i < BN * BK; i += NT) {
                int k = i / BN, n = i % BN;
                int gn = colBase + n;
                Bs[k][n] = (gn < N) ? B[(long)(k0 + k) * ldb + gn] : 0.f;
            }
        }
        __syncthreads();

        #pragma unroll
        for (int k = 0; k < BK; k++) {
            float a[TM], b[TN];
            #pragma unroll
            for (int i = 0; i < TM; i++) a[i] = As[k][ty * TM + i];
            #pragma unroll
            for (int j = 0; j < TN; j++) b[j] = Bs[k][tx * TN + j];
            #pragma unroll
            for (int i = 0; i < TM; i++)
                #pragma unroll
                for (int j = 0; j < TN; j++)
                    acc[i][j] += a[i] * b[j];
        }
        __syncthreads();
    }

    #pragma unroll
    for (int i = 0; i < TM; i++) {
        int gm = rowBase + ty * TM + i;
        if (gm >= M) continue;
        #pragma unroll
        for (int j = 0; j < TN; j++) {
            int gn = colBase + tx * TN + j;
            if (gn >= N) continue;
            float v = acc[i][j] * alpha;
            if (bias)  v += bias[gn];
            if (resid) v += resid[(long)gm * ldr + gn];
            C[(long)gm * ldc + gn] = v;
        }
    }
}

// ---------------- row softmax over 2048 columns (in place) ------------------
__global__ void softmax2048_kernel(float* __restrict__ S)
{
    float* row = S + (long)blockIdx.x * SEQ;
    int t = threadIdx.x;
    float v[8];
    float m = -1e30f;
    #pragma unroll
    for (int i = 0; i < 8; i++) { v[i] = row[t + i * 256]; m = fmaxf(m, v[i]); }

    __shared__ float red[256];
    red[t] = m; __syncthreads();
    for (int s = 128; s > 0; s >>= 1) {
        if (t < s) red[t] = fmaxf(red[t], red[t + s]);
        __syncthreads();
    }
    m = red[0];
    __syncthreads();

    float sum = 0.f;
    #pragma unroll
    for (int i = 0; i < 8; i++) { v[i] = __expf(v[i] - m); sum += v[i]; }
    red[t] = sum; __syncthreads();
    for (int s = 128; s > 0; s >>= 1) {
        if (t < s) red[t] += red[t + s];
        __syncthreads();
    }
    float inv = 1.f / red[0];
    #pragma unroll
    for (int i = 0; i < 8; i++) row[t + i * 256] = v[i] * inv;
}

// ---------------- concat [x | m] -> cat (rows of 512) -----------------------
__global__ void cat_kernel(const float* __restrict__ x, const float* __restrict__ m,
                           float* __restrict__ cat)
{
    long idx = (long)blockIdx.x * blockDim.x + threadIdx.x; // over ROWS*512
    long row = idx >> 9;
    int  c   = (int)(idx & 511);
    cat[idx] = (c < EMBED) ? x[row * EMBED + c] : m[row * EMBED + (c - EMBED)];
}

// ---------------- LayerNorm(512) + exact GELU, in place ---------------------
__global__ void ln_gelu_kernel(float* __restrict__ y,
                               const float* __restrict__ sc,
                               const float* __restrict__ bi)
{
    float* row = y + (long)blockIdx.x * (2 * EMBED);
    int t = threadIdx.x;
    float a = row[t], b = row[t + 256];

    __shared__ float red[256];
    red[t] = a + b; __syncthreads();
    for (int s = 128; s > 0; s >>= 1) {
        if (t < s) red[t] += red[t + s];
        __syncthreads();
    }
    float mean = red[0] * (1.f / 512.f);
    __syncthreads();

    float da = a - mean, db = b - mean;
    red[t] = da * da + db * db; __syncthreads();
    for (int s = 128; s > 0; s >>= 1) {
        if (t < s) red[t] += red[t + s];
        __syncthreads();
    }
    float inv = rsqrtf(red[0] * (1.f / 512.f) + 1e-5f);

    float g1 = da * inv * sc[t]       + bi[t];
    float g2 = db * inv * sc[t + 256] + bi[t + 256];
    row[t]       = 0.5f * g1 * (1.f + erff(g1 * 0.70710678118654752f));
    row[t + 256] = 0.5f * g2 * (1.f + erff(g2 * 0.70710678118654752f));
}

// ---------------- host-side launch helpers ----------------------------------
static void gemm64(const float* A, const float* B, const float* bias, const float* resid,
                   float* C, int M, int N, int K, int lda, int ldb, int ldc, int ldr,
                   long ao, long ai, long bo, long bi2, long co, long ci,
                   int H, int Z, float alpha, bool transB)
{
    dim3 grid((N + 63) / 64, (M + 63) / 64, Z);
    if (transB)
        gemm_kernel<64, 64, 4, 4, 1><<<grid, 256>>>(A, B, bias, resid, C, M, N, K,
            lda, ldb, ldc, ldr, ao, ai, bo, bi2, co, ci, H, alpha);
    else
        gemm_kernel<64, 64, 4, 4, 0><<<grid, 256>>>(A, B, bias, resid, C, M, N, K,
            lda, ldb, ldc, ldr, ao, ai, bo, bi2, co, ci, H, alpha);
}

static void gemm128(const float* A, const float* B, const float* bias, const float* resid,
                    float* C, int M, int N, int K, int lda, int ldb, int ldc, int ldr,
                    long ao, long ai, long bo, long bi2, long co, long ci,
                    int H, int Z, float alpha, bool transB)
{
    dim3 grid((N + 127) / 128, (M + 127) / 128, Z);
    if (transB)
        gemm_kernel<128, 128, 8, 8, 1><<<grid, 256>>>(A, B, bias, resid, C, M, N, K,
            lda, ldb, ldc, ldr, ao, ai, bo, bi2, co, ci, H, alpha);
    else
        gemm_kernel<128, 128, 8, 8, 0><<<grid, 256>>>(A, B, bias, resid, C, M, N, K,
            lda, ldb, ldc, ldr, ao, ai, bo, bi2, co, ci, H, alpha);
}

extern "C" void kernel_launch(void* const* d_in, const int* in_sizes, int n_in,
                              void* d_out, int out_size)
{
    const float* x0       = (const float*)d_in[0];
    const float* x1       = (const float*)d_in[1];
    const float* Wqk      = (const float*)d_in[2];
    const float* bqk      = (const float*)d_in[3];
    const float* Wv       = (const float*)d_in[4];
    const float* bv       = (const float*)d_in[5];
    const float* Wout     = (const float*)d_in[6];
    const float* bout     = (const float*)d_in[7];
    const float* W0       = (const float*)d_in[8];
    const float* b0       = (const float*)d_in[9];
    const float* ln_scale = (const float*)d_in[10];
    const float* ln_bias  = (const float*)d_in[11];
    const float* W3       = (const float*)d_in[12];
    const float* b3       = (const float*)d_in[13];
    float* out = (float*)d_out;

    float *qk0, *qk1, *v0, *v1, *S, *m0, *m1, *mo, *cat, *y;
    cudaGetSymbolAddress((void**)&qk0, g_qk0);
    cudaGetSymbolAddress((void**)&qk1, g_qk1);
    cudaGetSymbolAddress((void**)&v0,  g_v0);
    cudaGetSymbolAddress((void**)&v1,  g_v1);
    cudaGetSymbolAddress((void**)&S,   g_S);
    cudaGetSymbolAddress((void**)&m0,  g_m0);
    cudaGetSymbolAddress((void**)&m1,  g_m1);
    cudaGetSymbolAddress((void**)&mo,  g_mo);
    cudaGetSymbolAddress((void**)&cat, g_cat);
    cudaGetSymbolAddress((void**)&y,   g_y);

    const float attn_scale = 0.125f;         // 1/sqrt(64)
    const long  headOuter  = (long)SEQ * EMBED; // per-batch stride of [B,N,D]
    const long  headInner  = HDIM;              // per-head column offset

    // 1) input projections: qk = x@Wqk+bqk, v = x@Wv+bv  (M=8192,N=256,K=256)
    gemm64(x0, Wqk, bqk, nullptr, qk0, ROWS, EMBED, EMBED, EMBED, EMBED, EMBED, 0,
           0, 0, 0, 0, 0, 0, 1, 1, 1.f, false);
    gemm64(x1, Wqk, bqk, nullptr, qk1, ROWS, EMBED, EMBED, EMBED, EMBED, EMBED, 0,
           0, 0, 0, 0, 0, 0, 1, 1, 1.f, false);
    gemm64(x0, Wv, bv, nullptr, v0, ROWS, EMBED, EMBED, EMBED, EMBED, EMBED, 0,
           0, 0, 0, 0, 0, 0, 1, 1, 1.f, false);
    gemm64(x1, Wv, bv, nullptr, v1, ROWS, EMBED, EMBED, EMBED, EMBED, EMBED, 0,
           0, 0, 0, 0, 0, 0, 1, 1, 1.f, false);

    // 2) attention, direction 0: S = qk0 @ qk1^T * scale ; softmax rows ; m0 = S @ v1
    gemm128(qk0, qk1, nullptr, nullptr, S, SEQ, SEQ, HDIM, EMBED, EMBED, SEQ, 0,
            headOuter, headInner, headOuter, headInner,
            (long)NHEADS * NNL, NNL, NHEADS, BH, attn_scale, true);
    softmax2048_kernel<<<BH * SEQ, 256>>>(S);
    gemm64(S, v1, nullptr, nullptr, m0, SEQ, HDIM, SEQ, SEQ, EMBED, EMBED, 0,
           (long)NHEADS * NNL, NNL, headOuter, headInner, headOuter, headInner,
           NHEADS, BH, 1.f, false);

    // 3) attention, direction 1: S = qk1 @ qk0^T * scale ; softmax rows ; m1 = S @ v0
    gemm128(qk1, qk0, nullptr, nullptr, S, SEQ, SEQ, HDIM, EMBED, EMBED, SEQ, 0,
            headOuter, headInner, headOuter, headInner,
            (long)NHEADS * NNL, NNL, NHEADS, BH, attn_scale, true);
    softmax2048_kernel<<<BH * SEQ, 256>>>(S);
    gemm64(S, v0, nullptr, nullptr, m1, SEQ, HDIM, SEQ, SEQ, EMBED, EMBED, 0,
           (long)NHEADS * NNL, NNL, headOuter, headInner, headOuter, headInner,
           NHEADS, BH, 1.f, false);

    // 4) per-stream: out proj, concat-FFN with LN+GELU, residual
    for (int d = 0; d < 2; d++) {
        const float* x = d ? x1 : x0;
        const float* m = d ? m1 : m0;
        float* dst = out + (long)d * ROWS * EMBED;

        // mo = m @ Wout + bout
        gemm64(m, Wout, bout, nullptr, mo, ROWS, EMBED, EMBED, EMBED, EMBED, EMBED, 0,
               0, 0, 0, 0, 0, 0, 1, 1, 1.f, false);
        // cat = [x | mo]
        cat_kernel<<<(ROWS * 2 * EMBED) / 256, 256>>>(x, mo, cat);
        // y = cat @ W0 + b0  (M=8192,N=512,K=512)
        gemm128(cat, W0, b0, nullptr, y, ROWS, 2 * EMBED, 2 * EMBED,
                2 * EMBED, 2 * EMBED, 2 * EMBED, 0,
                0, 0, 0, 0, 0, 0, 1, 1, 1.f, false);
        // LayerNorm + GELU in place
        ln_gelu_kernel<<<ROWS, 256>>>(y, ln_scale, ln_bias);
        // dst = x + y @ W3 + b3
        gemm64(y, W3, b3, x, dst, ROWS, EMBED, 2 * EMBED,
               2 * EMBED, EMBED, EMBED, EMBED,
               0, 0, 0, 0, 0, 0, 1, 1, 1.f, false);
    }
}

// round 2
// speedup vs baseline: 2.4548x; 2.4548x over previous
#include <cuda_runtime.h>
#include <math.h>
#include <stdint.h>

// Problem constants
#define EMBED   256
#define NHEADS  4
#define HDIM    64
#define BATCHB  4
#define SEQ     2048
#define ROWS    (BATCHB*SEQ)          // 8192 rows per stream
#define BH      (BATCHB*NHEADS)       // 16 batched attention slices
#define NNL     ((long)SEQ*(long)SEQ) // 4,194,304 logits per slice

// ---------------- scratch (static device globals; no allocation) -----------
__device__ float g_qk0[ROWS*EMBED];
__device__ float g_qk1[ROWS*EMBED];
__device__ float g_v0 [ROWS*EMBED];
__device__ float g_v1 [ROWS*EMBED];
__device__ float g_S  [(long)BH*SEQ*SEQ];   // 256 MB logits buffer (reused per direction)
__device__ float g_m0 [ROWS*EMBED];
__device__ float g_m1 [ROWS*EMBED];
__device__ float g_mo [ROWS*EMBED];
__device__ float g_cat[ROWS*2*EMBED];
__device__ float g_y  [ROWS*2*EMBED];

// ---------------- tf32 helpers ----------------------------------------------
__device__ __forceinline__ float tf32r(float x) {
    uint32_t u;
    asm("cvt.rna.tf32.f32 %0, %1;" : "=r"(u) : "f"(x));
    return __uint_as_float(u);
}

__device__ __forceinline__ void mma_tf32(float d[4], const uint32_t a[4], const uint32_t b[2]) {
    asm volatile(
        "mma.sync.aligned.m16n8k8.row.col.f32.tf32.tf32.f32 "
        "{%0,%1,%2,%3},{%4,%5,%6,%7},{%8,%9},{%0,%1,%2,%3};"
        : "+f"(d[0]), "+f"(d[1]), "+f"(d[2]), "+f"(d[3])
        : "r"(a[0]), "r"(a[1]), "r"(a[2]), "r"(a[3]), "r"(b[0]), "r"(b[1]));
}

// ---------------- tensor-core tf32 GEMM -------------------------------------
// C[z] = alpha * A[z] @ op(B[z]) (+bias) (+resid)
// Batch offset per z: (z/H)*outer + (z%H)*inner  for A,B,C.
// All dims assumed to divide tile sizes exactly (true for this problem).
template<int BM, int BN, int WM, int WN, int TRANSB>
__global__ __launch_bounds__(256)
void mma_gemm(
    const float* __restrict__ A, const float* __restrict__ B,
    const float* __restrict__ bias, const float* __restrict__ resid,
    float* __restrict__ C,
    int M, int N, int K, int lda, int ldb, int ldc, int ldr,
    long aOuter, long aInner, long bOuter, long bInner, long cOuter, long cInner,
    int H, float alpha)
{
    constexpr int BK = 16;
    constexpr int LDS_ = BK + 4;                  // padded stride (conflict-free frags)
    constexpr int WN_TILES = WN / 8;
    constexpr int WM_TILES = WM / 16;
    constexpr int NWARPN = BN / WN;
    static_assert((BM / WM) * (BN / WN) == 8, "need 8 warps");

    __shared__ float As[BM][LDS_];
    __shared__ float Bs[BN][LDS_];

    int z  = blockIdx.z;
    int zo = z / H, zi = z % H;
    A += (long)zo * aOuter + (long)zi * aInner;
    B += (long)zo * bOuter + (long)zi * bInner;
    C += (long)zo * cOuter + (long)zi * cInner;

    const int tid  = threadIdx.x;
    const int warp = tid >> 5;
    const int lane = tid & 31;
    const int qr = lane >> 2;      // 0..7
    const int qc = lane & 3;       // 0..3

    const int rowBase = blockIdx.y * BM;
    const int colBase = blockIdx.x * BN;
    const int wm0 = (warp / NWARPN) * WM;
    const int wn0 = (warp % NWARPN) * WN;

    float acc[WM_TILES][WN_TILES][4];
    #pragma unroll
    for (int i = 0; i < WM_TILES; i++)
        #pragma unroll
        for (int j = 0; j < WN_TILES; j++)
            #pragma unroll
            for (int r = 0; r < 4; r++) acc[i][j][r] = 0.f;

    for (int k0 = 0; k0 < K; k0 += BK) {
        // ---- load A tile (BM x 16), float4 coalesced, tf32-round ----
        #pragma unroll
        for (int i = tid; i < BM * 4; i += 256) {
            int m  = i >> 2;
            int kg = i & 3;
            const float4 v = *(const float4*)(A + (long)(rowBase + m) * lda + k0 + kg * 4);
            As[m][kg * 4 + 0] = tf32r(v.x);
            As[m][kg * 4 + 1] = tf32r(v.y);
            As[m][kg * 4 + 2] = tf32r(v.z);
            As[m][kg * 4 + 3] = tf32r(v.w);
        }
        // ---- load B tile into Bs[n][k] ----
        if (TRANSB) {
            // B is [N][K] row-major: same pattern as A
            #pragma unroll
            for (int i = tid; i < BN * 4; i += 256) {
                int n  = i >> 2;
                int kg = i & 3;
                const float4 v = *(const float4*)(B + (long)(colBase + n) * ldb + k0 + kg * 4);
                Bs[n][kg * 4 + 0] = tf32r(v.x);
                Bs[n][kg * 4 + 1] = tf32r(v.y);
                Bs[n][kg * 4 + 2] = tf32r(v.z);
                Bs[n][kg * 4 + 3] = tf32r(v.w);
            }
        } else {
            // B is [K][N]: read coalesced along n, store transposed
            #pragma unroll
            for (int i = tid; i < BK * BN; i += 256) {
                int k = i / BN;
                int n = i % BN;
                Bs[n][k] = tf32r(B[(long)(k0 + k) * ldb + colBase + n]);
            }
        }
        __syncthreads();

        // ---- two k8 steps of mma ----
        #pragma unroll
        for (int ks = 0; ks < BK; ks += 8) {
            uint32_t af[WM_TILES][4];
            #pragma unroll
            for (int mt = 0; mt < WM_TILES; mt++) {
                int mr = wm0 + mt * 16;
                af[mt][0] = __float_as_uint(As[mr + qr    ][ks + qc]);
                af[mt][1] = __float_as_uint(As[mr + qr + 8][ks + qc]);
                af[mt][2] = __float_as_uint(As[mr + qr    ][ks + qc + 4]);
                af[mt][3] = __float_as_uint(As[mr + qr + 8][ks + qc + 4]);
            }
            uint32_t bf[WN_TILES][2];
            #pragma unroll
            for (int nt = 0; nt < WN_TILES; nt++) {
                int nr = wn0 + nt * 8;
                bf[nt][0] = __float_as_uint(Bs[nr + qr][ks + qc]);
                bf[nt][1] = __float_as_uint(Bs[nr + qr][ks + qc + 4]);
            }
            #pragma unroll
            for (int mt = 0; mt < WM_TILES; mt++)
                #pragma unroll
                for (int nt = 0; nt < WN_TILES; nt++)
                    mma_tf32(acc[mt][nt], af[mt], bf[nt]);
        }
        __syncthreads();
    }

    // ---- epilogue ----
    #pragma unroll
    for (int mt = 0; mt < WM_TILES; mt++) {
        #pragma unroll
        for (int nt = 0; nt < WN_TILES; nt++) {
            int gm = rowBase + wm0 + mt * 16 + qr;
            int gn = colBase + wn0 + nt * 8 + qc * 2;
            float b0 = 0.f, b1 = 0.f;
            if (bias) { b0 = bias[gn]; b1 = bias[gn + 1]; }
            float v0 = acc[mt][nt][0] * alpha + b0;
            float v1 = acc[mt][nt][1] * alpha + b1;
            float v2 = acc[mt][nt][2] * alpha + b0;
            float v3 = acc[mt][nt][3] * alpha + b1;
            if (resid) {
                const float2 r0 = *(const float2*)(resid + (long)gm * ldr + gn);
                const float2 r1 = *(const float2*)(resid + (long)(gm + 8) * ldr + gn);
                v0 += r0.x; v1 += r0.y; v2 += r1.x; v3 += r1.y;
            }
            *(float2*)(C + (long)gm * ldc + gn)       = make_float2(v0, v1);
            *(float2*)(C + (long)(gm + 8) * ldc + gn) = make_float2(v2, v3);
        }
    }
}

// ---------------- row softmax over 2048 columns (in place) ------------------
__global__ void softmax2048_kernel(float* __restrict__ S)
{
    float* row = S + (long)blockIdx.x * SEQ;
    int t = threadIdx.x;
    float v[8];
    float m = -1e30f;
    #pragma unroll
    for (int i = 0; i < 8; i++) { v[i] = row[t + i * 256]; m = fmaxf(m, v[i]); }

    __shared__ float red[256];
    red[t] = m; __syncthreads();
    for (int s = 128; s > 0; s >>= 1) {
        if (t < s) red[t] = fmaxf(red[t], red[t + s]);
        __syncthreads();
    }
    m = red[0];
    __syncthreads();

    float sum = 0.f;
    #pragma unroll
    for (int i = 0; i < 8; i++) { v[i] = __expf(v[i] - m); sum += v[i]; }
    red[t] = sum; __syncthreads();
    for (int s = 128; s > 0; s >>= 1) {
        if (t < s) red[t] += red[t + s];
        __syncthreads();
    }
    float inv = 1.f / red[0];
    #pragma unroll
    for (int i = 0; i < 8; i++) row[t + i * 256] = v[i] * inv;
}

// ---------------- concat [x | m] -> cat (rows of 512) -----------------------
__global__ void cat_kernel(const float* __restrict__ x, const float* __restrict__ m,
                           float* __restrict__ cat)
{
    long idx = (long)blockIdx.x * blockDim.x + threadIdx.x; // over ROWS*512
    long row = idx >> 9;
    int  c   = (int)(idx & 511);
    cat[idx] = (c < EMBED) ? x[row * EMBED + c] : m[row * EMBED + (c - EMBED)];
}

// ---------------- LayerNorm(512) + exact GELU, in place ---------------------
__global__ void ln_gelu_kernel(float* __restrict__ y,
                               const float* __restrict__ sc,
                               const float* __restrict__ bi)
{
    float* row = y + (long)blockIdx.x * (2 * EMBED);
    int t = threadIdx.x;
    float a = row[t], b = row[t + 256];

    __shared__ float red[256];
    red[t] = a + b; __syncthreads();
    for (int s = 128; s > 0; s >>= 1) {
        if (t < s) red[t] += red[t + s];
        __syncthreads();
    }
    float mean = red[0] * (1.f / 512.f);
    __syncthreads();

    float da = a - mean, db = b - mean;
    red[t] = da * da + db * db; __syncthreads();
    for (int s = 128; s > 0; s >>= 1) {
        if (t < s) red[t] += red[t + s];
        __syncthreads();
    }
    float inv = rsqrtf(red[0] * (1.f / 512.f) + 1e-5f);

    float g1 = da * inv * sc[t]       + bi[t];
    float g2 = db * inv * sc[t + 256] + bi[t + 256];
    row[t]       = 0.5f * g1 * (1.f + erff(g1 * 0.70710678118654752f));
    row[t + 256] = 0.5f * g2 * (1.f + erff(g2 * 0.70710678118654752f));
}

// ---------------- host-side launch helpers ----------------------------------
static void tc_gemm(const float* A, const float* B, const float* bias, const float* resid,
                    float* C, int M, int N, int K, int lda, int ldb, int ldc, int ldr,
                    long ao, long ai, long bo, long bi2, long co, long ci,
                    int H, int Z, float alpha, bool transB, bool narrow)
{
    if (narrow) {
        // 128x64 tiles (PV GEMM, N=64)
        dim3 grid(N / 64, M / 128, Z);
        if (transB)
            mma_gemm<128, 64, 32, 32, 1><<<grid, 256>>>(A, B, bias, resid, C, M, N, K,
                lda, ldb, ldc, ldr, ao, ai, bo, bi2, co, ci, H, alpha);
        else
            mma_gemm<128, 64, 32, 32, 0><<<grid, 256>>>(A, B, bias, resid, C, M, N, K,
                lda, ldb, ldc, ldr, ao, ai, bo, bi2, co, ci, H, alpha);
    } else {
        dim3 grid(N / 128, M / 128, Z);
        if (transB)
            mma_gemm<128, 128, 32, 64, 1><<<grid, 256>>>(A, B, bias, resid, C, M, N, K,
                lda, ldb, ldc, ldr, ao, ai, bo, bi2, co, ci, H, alpha);
        else
            mma_gemm<128, 128, 32, 64, 0><<<grid, 256>>>(A, B, bias, resid, C, M, N, K,
                lda, ldb, ldc, ldr, ao, ai, bo, bi2, co, ci, H, alpha);
    }
}

extern "C" void kernel_launch(void* const* d_in, const int* in_sizes, int n_in,
                              void* d_out, int out_size)
{
    const float* x0       = (const float*)d_in[0];
    const float* x1       = (const float*)d_in[1];
    const float* Wqk      = (const float*)d_in[2];
    const float* bqk      = (const float*)d_in[3];
    const float* Wv       = (const float*)d_in[4];
    const float* bv       = (const float*)d_in[5];
    const float* Wout     = (const float*)d_in[6];
    const float* bout     = (const float*)d_in[7];
    const float* W0       = (const float*)d_in[8];
    const float* b0       = (const float*)d_in[9];
    const float* ln_scale = (const float*)d_in[10];
    const float* ln_bias  = (const float*)d_in[11];
    const float* W3       = (const float*)d_in[12];
    const float* b3       = (const float*)d_in[13];
    float* out = (float*)d_out;

    float *qk0, *qk1, *v0, *v1, *S, *m0, *m1, *mo, *cat, *y;
    cudaGetSymbolAddress((void**)&qk0, g_qk0);
    cudaGetSymbolAddress((void**)&qk1, g_qk1);
    cudaGetSymbolAddress((void**)&v0,  g_v0);
    cudaGetSymbolAddress((void**)&v1,  g_v1);
    cudaGetSymbolAddress((void**)&S,   g_S);
    cudaGetSymbolAddress((void**)&m0,  g_m0);
    cudaGetSymbolAddress((void**)&m1,  g_m1);
    cudaGetSymbolAddress((void**)&mo,  g_mo);
    cudaGetSymbolAddress((void**)&cat, g_cat);
    cudaGetSymbolAddress((void**)&y,   g_y);

    const float attn_scale = 0.125f;            // 1/sqrt(64)
    const long  headOuter  = (long)SEQ * EMBED; // per-batch stride of [B,N,D]
    const long  headInner  = HDIM;              // per-head column offset

    // 1) input projections
    tc_gemm(x0, Wqk, bqk, nullptr, qk0, ROWS, EMBED, EMBED, EMBED, EMBED, EMBED, 0,
            0, 0, 0, 0, 0, 0, 1, 1, 1.f, false, false);
    tc_gemm(x1, Wqk, bqk, nullptr, qk1, ROWS, EMBED, EMBED, EMBED, EMBED, EMBED, 0,
            0, 0, 0, 0, 0, 0, 1, 1, 1.f, false, false);
    tc_gemm(x0, Wv, bv, nullptr, v0, ROWS, EMBED, EMBED, EMBED, EMBED, EMBED, 0,
            0, 0, 0, 0, 0, 0, 1, 1, 1.f, false, false);
    tc_gemm(x1, Wv, bv, nullptr, v1, ROWS, EMBED, EMBED, EMBED, EMBED, EMBED, 0,
            0, 0, 0, 0, 0, 0, 1, 1, 1.f, false, false);

    // 2) attention dir 0: S = qk0 @ qk1^T * scale ; softmax ; m0 = S @ v1
    tc_gemm(qk0, qk1, nullptr, nullptr, S, SEQ, SEQ, HDIM, EMBED, EMBED, SEQ, 0,
            headOuter, headInner, headOuter, headInner,
            (long)NHEADS * NNL, NNL, NHEADS, BH, attn_scale, true, false);
    softmax2048_kernel<<<BH * SEQ, 256>>>(S);
    tc_gemm(S, v1, nullptr, nullptr, m0, SEQ, HDIM, SEQ, SEQ, EMBED, EMBED, 0,
            (long)NHEADS * NNL, NNL, headOuter, headInner, headOuter, headInner,
            NHEADS, BH, 1.f, false, true);

    // 3) attention dir 1
    tc_gemm(qk1, qk0, nullptr, nullptr, S, SEQ, SEQ, HDIM, EMBED, EMBED, SEQ, 0,
            headOuter, headInner, headOuter, headInner,
            (long)NHEADS * NNL, NNL, NHEADS, BH, attn_scale, true, false);
    softmax2048_kernel<<<BH * SEQ, 256>>>(S);
    tc_gemm(S, v0, nullptr, nullptr, m1, SEQ, HDIM, SEQ, SEQ, EMBED, EMBED, 0,
            (long)NHEADS * NNL, NNL, headOuter, headInner, headOuter, headInner,
            NHEADS, BH, 1.f, false, true);

    // 4) per-stream: out proj, concat-FFN with LN+GELU, residual
    for (int d = 0; d < 2; d++) {
        const float* x = d ? x1 : x0;
        const float* m = d ? m1 : m0;
        float* dst = out + (long)d * ROWS * EMBED;

        tc_gemm(m, Wout, bout, nullptr, mo, ROWS, EMBED, EMBED, EMBED, EMBED, EMBED, 0,
                0, 0, 0, 0, 0, 0, 1, 1, 1.f, false, false);
        cat_kernel<<<(ROWS * 2 * EMBED) / 256, 256>>>(x, mo, cat);
        tc_gemm(cat, W0, b0, nullptr, y, ROWS, 2 * EMBED, 2 * EMBED,
                2 * EMBED, 2 * EMBED, 2 * EMBED, 0,
                0, 0, 0, 0, 0, 0, 1, 1, 1.f, false, false);
        ln_gelu_kernel<<<ROWS, 256>>>(y, ln_scale, ln_bias);
        tc_gemm(y, W3, b3, x, dst, ROWS, EMBED, 2 * EMBED,
                2 * EMBED, EMBED, EMBED, EMBED,
                0, 0, 0, 0, 0, 0, 1, 1, 1.f, false, false);
    }
}

// round 3
// speedup vs baseline: 3.7732x; 1.5371x over previous
#include <cuda_runtime.h>
#include <math.h>
#include <stdint.h>

// Problem constants
#define EMBED   256
#define NHEADS  4
#define HDIM    64
#define BATCHB  4
#define SEQ     2048
#define ROWS    (BATCHB*SEQ)          // 8192 rows per stream
#define BH      (BATCHB*NHEADS)       // 16 batched attention slices

// ---------------- scratch (static device globals; no allocation) -----------
__device__ float g_qk0[ROWS*EMBED];
__device__ float g_qk1[ROWS*EMBED];
__device__ float g_v0 [ROWS*EMBED];
__device__ float g_v1 [ROWS*EMBED];
__device__ float g_m0 [ROWS*EMBED];
__device__ float g_m1 [ROWS*EMBED];
__device__ float g_mo [ROWS*EMBED];
__device__ float g_y  [ROWS*2*EMBED];

// ---------------- tf32 helpers ----------------------------------------------
__device__ __forceinline__ float tf32r(float x) {
    uint32_t u;
    asm("cvt.rna.tf32.f32 %0, %1;" : "=r"(u) : "f"(x));
    return __uint_as_float(u);
}

__device__ __forceinline__ void mma_tf32(float d[4], const uint32_t a[4], const uint32_t b[2]) {
    asm volatile(
        "mma.sync.aligned.m16n8k8.row.col.f32.tf32.tf32.f32 "
        "{%0,%1,%2,%3},{%4,%5,%6,%7},{%8,%9},{%0,%1,%2,%3};"
        : "+f"(d[0]), "+f"(d[1]), "+f"(d[2]), "+f"(d[3])
        : "r"(a[0]), "r"(a[1]), "r"(a[2]), "r"(a[3]), "r"(b[0]), "r"(b[1]));
}

// ---------------- fused flash cross-attention --------------------------------
// O = softmax(Q K^T * 0.125) V   for one (batch, head) slice.
// Q,K,V,O are [SEQ][EMBED] row-major with head column offset; hd = 64.
// CTA: 64 query rows, 4 warps x 16 rows. Loop over key blocks of 64.
#define FSTR 68   // smem row stride (conflict-free fragment LDS)

__global__ __launch_bounds__(128)
void flash_kernel(const float* __restrict__ Qg, const float* __restrict__ Kg,
                  const float* __restrict__ Vg, float* __restrict__ Og)
{
    extern __shared__ float sm[];
    float (*Ps)[FSTR] = (float(*)[FSTR])sm;               // Q staging, then P
    float (*Ks)[FSTR] = (float(*)[FSTR])(sm + 64*FSTR);   // K: [key][hd]
    float (*Vs)[FSTR] = (float(*)[FSTR])(sm + 2*64*FSTR); // V transposed: [hd][key]

    const long base = (long)(blockIdx.y >> 2) * SEQ * EMBED + (blockIdx.y & 3) * HDIM;
    const float* Qp = Qg + base + (long)blockIdx.x * 64 * EMBED;
    const float* K0 = Kg + base;
    const float* V0 = Vg + base;
    float*       Op = Og + base + (long)blockIdx.x * 64 * EMBED;

    const int tid  = threadIdx.x;
    const int warp = tid >> 5;
    const int lane = tid & 31;
    const int qr = lane >> 2, qc = lane & 3;
    const int mr = warp * 16;

    // ---- stage Q tile (64x64) in smem, preload A-fragments to registers ----
    #pragma unroll
    for (int i = tid; i < 64 * 16; i += 128) {
        int r = i >> 4, c4 = (i & 15) * 4;
        float4 v = *(const float4*)(Qp + (long)r * EMBED + c4);
        Ps[r][c4+0] = tf32r(v.x); Ps[r][c4+1] = tf32r(v.y);
        Ps[r][c4+2] = tf32r(v.z); Ps[r][c4+3] = tf32r(v.w);
    }
    __syncthreads();
    uint32_t qf[8][4];
    #pragma unroll
    for (int ks = 0; ks < 8; ks++) {
        qf[ks][0] = __float_as_uint(Ps[mr+qr  ][ks*8+qc  ]);
        qf[ks][1] = __float_as_uint(Ps[mr+qr+8][ks*8+qc  ]);
        qf[ks][2] = __float_as_uint(Ps[mr+qr  ][ks*8+qc+4]);
        qf[ks][3] = __float_as_uint(Ps[mr+qr+8][ks*8+qc+4]);
    }
    __syncthreads();   // everyone done reading Q before Ps is reused for P

    float oacc[8][4];
    #pragma unroll
    for (int nt = 0; nt < 8; nt++)
        #pragma unroll
        for (int j = 0; j < 4; j++) oacc[nt][j] = 0.f;
    float mrow0 = -1e30f, mrow1 = -1e30f, lrow0 = 0.f, lrow1 = 0.f;

    for (int kb = 0; kb < SEQ / 64; kb++) {
        const float* Kp = K0 + (long)kb * 64 * EMBED;
        const float* Vp = V0 + (long)kb * 64 * EMBED;
        #pragma unroll
        for (int i = tid; i < 64 * 16; i += 128) {
            int r = i >> 4, c4 = (i & 15) * 4;
            float4 kv = *(const float4*)(Kp + (long)r * EMBED + c4);
            float4 vv = *(const float4*)(Vp + (long)r * EMBED + c4);
            Ks[r][c4+0] = tf32r(kv.x); Ks[r][c4+1] = tf32r(kv.y);
            Ks[r][c4+2] = tf32r(kv.z); Ks[r][c4+3] = tf32r(kv.w);
            Vs[c4+0][r] = tf32r(vv.x); Vs[c4+1][r] = tf32r(vv.y);
            Vs[c4+2][r] = tf32r(vv.z); Vs[c4+3][r] = tf32r(vv.w);
        }
        __syncthreads();

        // ---- S = Q K^T (16x64 per warp) ----
        float s[8][4];
        #pragma unroll
        for (int nt = 0; nt < 8; nt++)
            #pragma unroll
            for (int j = 0; j < 4; j++) s[nt][j] = 0.f;
        #pragma unroll
        for (int ks = 0; ks < 8; ks++) {
            #pragma unroll
            for (int nt = 0; nt < 8; nt++) {
                uint32_t bb[2] = { __float_as_uint(Ks[nt*8+qr][ks*8+qc]),
                                   __float_as_uint(Ks[nt*8+qr][ks*8+qc+4]) };
                mma_tf32(s[nt], qf[ks], bb);
            }
        }

        // ---- online softmax (rows qr, qr+8) ----
        float mx0 = -1e30f, mx1 = -1e30f;
        #pragma unroll
        for (int nt = 0; nt < 8; nt++) {
            s[nt][0] *= 0.125f; s[nt][1] *= 0.125f;
            s[nt][2] *= 0.125f; s[nt][3] *= 0.125f;
            mx0 = fmaxf(mx0, fmaxf(s[nt][0], s[nt][1]));
            mx1 = fmaxf(mx1, fmaxf(s[nt][2], s[nt][3]));
        }
        mx0 = fmaxf(mx0, __shfl_xor_sync(0xffffffffu, mx0, 1));
        mx0 = fmaxf(mx0, __shfl_xor_sync(0xffffffffu, mx0, 2));
        mx1 = fmaxf(mx1, __shfl_xor_sync(0xffffffffu, mx1, 1));
        mx1 = fmaxf(mx1, __shfl_xor_sync(0xffffffffu, mx1, 2));
        float mn0 = fmaxf(mrow0, mx0), mn1 = fmaxf(mrow1, mx1);
        float a0 = __expf(mrow0 - mn0), a1 = __expf(mrow1 - mn1);
        float sum0 = 0.f, sum1 = 0.f;
        #pragma unroll
        for (int nt = 0; nt < 8; nt++) {
            s[nt][0] = __expf(s[nt][0] - mn0); sum0 += s[nt][0];
            s[nt][1] = __expf(s[nt][1] - mn0); sum0 += s[nt][1];
            s[nt][2] = __expf(s[nt][2] - mn1); sum1 += s[nt][2];
            s[nt][3] = __expf(s[nt][3] - mn1); sum1 += s[nt][3];
        }
        sum0 += __shfl_xor_sync(0xffffffffu, sum0, 1);
        sum0 += __shfl_xor_sync(0xffffffffu, sum0, 2);
        sum1 += __shfl_xor_sync(0xffffffffu, sum1, 1);
        sum1 += __shfl_xor_sync(0xffffffffu, sum1, 2);
        lrow0 = lrow0 * a0 + sum0;  lrow1 = lrow1 * a1 + sum1;
        mrow0 = mn0;                mrow1 = mn1;
        #pragma unroll
        for (int nt = 0; nt < 8; nt++) {
            oacc[nt][0] *= a0; oacc[nt][1] *= a0;
            oacc[nt][2] *= a1; oacc[nt][3] *= a1;
        }

        // ---- P -> smem (warp-private rows), then O += P V ----
        #pragma unroll
        for (int nt = 0; nt < 8; nt++) {
            Ps[mr+qr  ][nt*8+qc*2  ] = tf32r(s[nt][0]);
            Ps[mr+qr  ][nt*8+qc*2+1] = tf32r(s[nt][1]);
            Ps[mr+qr+8][nt*8+qc*2  ] = tf32r(s[nt][2]);
            Ps[mr+qr+8][nt*8+qc*2+1] = tf32r(s[nt][3]);
        }
        __syncwarp();
        #pragma unroll
        for (int ks = 0; ks < 8; ks++) {
            uint32_t af[4] = {
                __float_as_uint(Ps[mr+qr  ][ks*8+qc  ]),
                __float_as_uint(Ps[mr+qr+8][ks*8+qc  ]),
                __float_as_uint(Ps[mr+qr  ][ks*8+qc+4]),
                __float_as_uint(Ps[mr+qr+8][ks*8+qc+4]) };
            #pragma unroll
            for (int nt = 0; nt < 8; nt++) {
                uint32_t bb[2] = { __float_as_uint(Vs[nt*8+qr][ks*8+qc]),
                                   __float_as_uint(Vs[nt*8+qr][ks*8+qc+4]) };
                mma_tf32(oacc[nt], af, bb);
            }
        }
        __syncthreads();   // protect K/V before next iteration overwrites
    }

    // ---- epilogue: normalize and write O ----
    float inv0 = 1.f / lrow0, inv1 = 1.f / lrow1;
    #pragma unroll
    for (int nt = 0; nt < 8; nt++) {
        int col = nt * 8 + qc * 2;
        *(float2*)(Op + (long)(mr+qr  ) * EMBED + col) =
            make_float2(oacc[nt][0] * inv0, oacc[nt][1] * inv0);
        *(float2*)(Op + (long)(mr+qr+8) * EMBED + col) =
            make_float2(oacc[nt][2] * inv1, oacc[nt][3] * inv1);
    }
}

// ---------------- tensor-core tf32 GEMM (dense, row-major B) -----------------
// C = A @ B + bias (+resid). M,N,K multiples of tile sizes.
template<int BM, int BN, int WM, int WN>
__global__ __launch_bounds__(256)
void mma_gemm(
    const float* __restrict__ A, const float* __restrict__ B,
    const float* __restrict__ bias, const float* __restrict__ resid,
    float* __restrict__ C,
    int M, int N, int K, int lda, int ldb, int ldc, int ldr)
{
    constexpr int BK = 16;
    constexpr int LDS_ = BK + 4;
    constexpr int WN_TILES = WN / 8;
    constexpr int WM_TILES = WM / 16;
    constexpr int NWARPN = BN / WN;

    __shared__ float As[BM][LDS_];
    __shared__ float Bs[BN][LDS_];

    const int tid  = threadIdx.x;
    const int warp = tid >> 5;
    const int lane = tid & 31;
    const int qr = lane >> 2;
    const int qc = lane & 3;

    const int rowBase = blockIdx.y * BM;
    const int colBase = blockIdx.x * BN;
    const int wm0 = (warp / NWARPN) * WM;
    const int wn0 = (warp % NWARPN) * WN;

    float acc[WM_TILES][WN_TILES][4];
    #pragma unroll
    for (int i = 0; i < WM_TILES; i++)
        #pragma unroll
        for (int j = 0; j < WN_TILES; j++)
            #pragma unroll
            for (int r = 0; r < 4; r++) acc[i][j][r] = 0.f;

    for (int k0 = 0; k0 < K; k0 += BK) {
        #pragma unroll
        for (int i = tid; i < BM * 4; i += 256) {
            int m  = i >> 2;
            int kg = i & 3;
            const float4 v = *(const float4*)(A + (long)(rowBase + m) * lda + k0 + kg * 4);
            As[m][kg*4+0] = tf32r(v.x); As[m][kg*4+1] = tf32r(v.y);
            As[m][kg*4+2] = tf32r(v.z); As[m][kg*4+3] = tf32r(v.w);
        }
        #pragma unroll
        for (int i = tid; i < BK * BN; i += 256) {
            int k = i / BN;
            int n = i % BN;
            Bs[n][k] = tf32r(B[(long)(k0 + k) * ldb + colBase + n]);
        }
        __syncthreads();

        #pragma unroll
        for (int ks = 0; ks < BK; ks += 8) {
            uint32_t af[WM_TILES][4];
            #pragma unroll
            for (int mt = 0; mt < WM_TILES; mt++) {
                int mrr = wm0 + mt * 16;
                af[mt][0] = __float_as_uint(As[mrr + qr    ][ks + qc]);
                af[mt][1] = __float_as_uint(As[mrr + qr + 8][ks + qc]);
                af[mt][2] = __float_as_uint(As[mrr + qr    ][ks + qc + 4]);
                af[mt][3] = __float_as_uint(As[mrr + qr + 8][ks + qc + 4]);
            }
            uint32_t bf[WN_TILES][2];
            #pragma unroll
            for (int nt = 0; nt < WN_TILES; nt++) {
                int nr = wn0 + nt * 8;
                bf[nt][0] = __float_as_uint(Bs[nr + qr][ks + qc]);
                bf[nt][1] = __float_as_uint(Bs[nr + qr][ks + qc + 4]);
            }
            #pragma unroll
            for (int mt = 0; mt < WM_TILES; mt++)
                #pragma unroll
                for (int nt = 0; nt < WN_TILES; nt++)
                    mma_tf32(acc[mt][nt], af[mt], bf[nt]);
        }
        __syncthreads();
    }

    #pragma unroll
    for (int mt = 0; mt < WM_TILES; mt++) {
        #pragma unroll
        for (int nt = 0; nt < WN_TILES; nt++) {
            int gm = rowBase + wm0 + mt * 16 + qr;
            int gn = colBase + wn0 + nt * 8 + qc * 2;
            float b0 = 0.f, b1 = 0.f;
            if (bias) { b0 = bias[gn]; b1 = bias[gn + 1]; }
            float v0 = acc[mt][nt][0] + b0;
            float v1 = acc[mt][nt][1] + b1;
            float v2 = acc[mt][nt][2] + b0;
            float v3 = acc[mt][nt][3] + b1;
            if (resid) {
                const float2 r0 = *(const float2*)(resid + (long)gm * ldr + gn);
                const float2 r1 = *(const float2*)(resid + (long)(gm + 8) * ldr + gn);
                v0 += r0.x; v1 += r0.y; v2 += r1.x; v3 += r1.y;
            }
            *(float2*)(C + (long)gm * ldc + gn)       = make_float2(v0, v1);
            *(float2*)(C + (long)(gm + 8) * ldc + gn) = make_float2(v2, v3);
        }
    }
}

// ---------------- LayerNorm(512) + exact GELU, in place ---------------------
__global__ void ln_gelu_kernel(float* __restrict__ y,
                               const float* __restrict__ sc,
                               const float* __restrict__ bi)
{
    float* row = y + (long)blockIdx.x * (2 * EMBED);
    int t = threadIdx.x;
    float a = row[t], b = row[t + 256];

    __shared__ float red[256];
    red[t] = a + b; __syncthreads();
    for (int s = 128; s > 0; s >>= 1) {
        if (t < s) red[t] += red[t + s];
        __syncthreads();
    }
    float mean = red[0] * (1.f / 512.f);
    __syncthreads();

    float da = a - mean, db = b - mean;
    red[t] = da * da + db * db; __syncthreads();
    for (int s = 128; s > 0; s >>= 1) {
        if (t < s) red[t] += red[t + s];
        __syncthreads();
    }
    float inv = rsqrtf(red[0] * (1.f / 512.f) + 1e-5f);

    float g1 = da * inv * sc[t]       + bi[t];
    float g2 = db * inv * sc[t + 256] + bi[t + 256];
    row[t]       = 0.5f * g1 * (1.f + erff(g1 * 0.70710678118654752f));
    row[t + 256] = 0.5f * g2 * (1.f + erff(g2 * 0.70710678118654752f));
}

// ---------------- host side --------------------------------------------------
static void tc_gemm(const float* A, const float* B, const float* bias, const float* resid,
                    float* C, int M, int N, int K, int lda, int ldb, int ldc, int ldr)
{
    dim3 grid(N / 128, M / 128, 1);
    mma_gemm<128, 128, 32, 64><<<grid, 256>>>(A, B, bias, resid, C,
                                              M, N, K, lda, ldb, ldc, ldr);
}

extern "C" void kernel_launch(void* const* d_in, const int* in_sizes, int n_in,
                              void* d_out, int out_size)
{
    const float* x0       = (const float*)d_in[0];
    const float* x1       = (const float*)d_in[1];
    const float* Wqk      = (const float*)d_in[2];
    const float* bqk      = (const float*)d_in[3];
    const float* Wv       = (const float*)d_in[4];
    const float* bv       = (const float*)d_in[5];
    const float* Wout     = (const float*)d_in[6];
    const float* bout     = (const float*)d_in[7];
    const float* W0       = (const float*)d_in[8];
    const float* b0       = (const float*)d_in[9];
    const float* ln_scale = (const float*)d_in[10];
    const float* ln_bias  = (const float*)d_in[11];
    const float* W3       = (const float*)d_in[12];
    const float* b3       = (const float*)d_in[13];
    float* out = (float*)d_out;

    float *qk0, *qk1, *v0, *v1, *m0, *m1, *mo, *y;
    cudaGetSymbolAddress((void**)&qk0, g_qk0);
    cudaGetSymbolAddress((void**)&qk1, g_qk1);
    cudaGetSymbolAddress((void**)&v0,  g_v0);
    cudaGetSymbolAddress((void**)&v1,  g_v1);
    cudaGetSymbolAddress((void**)&m0,  g_m0);
    cudaGetSymbolAddress((void**)&m1,  g_m1);
    cudaGetSymbolAddress((void**)&mo,  g_mo);
    cudaGetSymbolAddress((void**)&y,   g_y);

    const int FLASH_SMEM = 3 * 64 * FSTR * sizeof(float);   // 52224 B
    cudaFuncSetAttribute(flash_kernel,
                         cudaFuncAttributeMaxDynamicSharedMemorySize, FLASH_SMEM);

    // 1) input projections (M=8192, N=256, K=256)
    tc_gemm(x0, Wqk, bqk, nullptr, qk0, ROWS, EMBED, EMBED, EMBED, EMBED, EMBED, 0);
    tc_gemm(x1, Wqk, bqk, nullptr, qk1, ROWS, EMBED, EMBED, EMBED, EMBED, EMBED, 0);
    tc_gemm(x0, Wv,  bv,  nullptr, v0,  ROWS, EMBED, EMBED, EMBED, EMBED, EMBED, 0);
    tc_gemm(x1, Wv,  bv,  nullptr, v1,  ROWS, EMBED, EMBED, EMBED, EMBED, EMBED, 0);

    // 2) fused flash cross-attention, both directions
    dim3 fgrid(SEQ / 64, BH, 1);
    flash_kernel<<<fgrid, 128, FLASH_SMEM>>>(qk0, qk1, v1, m0);
    flash_kernel<<<fgrid, 128, FLASH_SMEM>>>(qk1, qk0, v0, m1);

    // 3) per-stream: out proj, split-W0 FFN with LN+GELU, residual
    for (int d = 0; d < 2; d++) {
        const float* x = d ? x1 : x0;
        const float* m = d ? m1 : m0;
        float* dst = out + (long)d * ROWS * EMBED;

        // mo = m @ Wout + bout
        tc_gemm(m, Wout, bout, nullptr, mo, ROWS, EMBED, EMBED, EMBED, EMBED, EMBED, 0);
        // y = x @ W0_top + b0 ;  y += mo @ W0_bot   (replaces concat)
        tc_gemm(x,  W0,               b0,      nullptr, y, ROWS, 2*EMBED, EMBED,
                EMBED, 2*EMBED, 2*EMBED, 0);
        tc_gemm(mo, W0 + EMBED*2*EMBED, nullptr, y,     y, ROWS, 2*EMBED, EMBED,
                EMBED, 2*EMBED, 2*EMBED, 2*EMBED);
        // LayerNorm + GELU in place
        ln_gelu_kernel<<<ROWS, 256>>>(y, ln_scale, ln_bias);
        // dst = x + y @ W3 + b3
        tc_gemm(y, W3, b3, x, dst, ROWS, EMBED, 2*EMBED, 2*EMBED, EMBED, EMBED, EMBED);
    }
}

// round 4
// speedup vs baseline: 6.1285x; 1.6242x over previous
#include <cuda_runtime.h>
#include <math.h>
#include <stdint.h>

// Problem constants
#define EMBED   256
#define NHEADS  4
#define HDIM    64
#define BATCHB  4
#define SEQ     2048
#define ROWS    (BATCHB*SEQ)          // 8192 rows per stream
#define BH      (BATCHB*NHEADS)       // 16 batched attention slices
#define SZ      ((long)ROWS*EMBED)    // 2M floats per [ROWS][EMBED] tensor

// ---------------- scratch (static device globals; no allocation) -----------
__device__ float g_qkv[4*SZ];         // qk0, qk1, v0, v1  (tf32-rounded)
__device__ float g_m  [2*SZ];         // attention outputs m0, m1
__device__ float g_mo [2*SZ];         // after Wout
__device__ float g_y  [2L*ROWS*512];  // FFN hidden

// ---------------- helpers ----------------------------------------------------
__device__ __forceinline__ float tf32r(float x) {
    uint32_t u;
    asm("cvt.rna.tf32.f32 %0, %1;" : "=r"(u) : "f"(x));
    return __uint_as_float(u);
}
__device__ __forceinline__ uint32_t tf32u(float x) {
    uint32_t u;
    asm("cvt.rna.tf32.f32 %0, %1;" : "=r"(u) : "f"(x));
    return u;
}
__device__ __forceinline__ void mma_tf32(float d[4], const uint32_t a[4], const uint32_t b[2]) {
    asm volatile(
        "mma.sync.aligned.m16n8k8.row.col.f32.tf32.tf32.f32 "
        "{%0,%1,%2,%3},{%4,%5,%6,%7},{%8,%9},{%0,%1,%2,%3};"
        : "+f"(d[0]), "+f"(d[1]), "+f"(d[2]), "+f"(d[3])
        : "r"(a[0]), "r"(a[1]), "r"(a[2]), "r"(a[3]), "r"(b[0]), "r"(b[1]));
}
__device__ __forceinline__ void cpa16(void* smem, const void* gmem) {
    uint32_t s = (uint32_t)__cvta_generic_to_shared(smem);
    asm volatile("cp.async.cg.shared.global [%0], [%1], 16;" :: "r"(s), "l"(gmem));
}
__device__ __forceinline__ void cp_commit() { asm volatile("cp.async.commit_group;"); }
__device__ __forceinline__ void cp_wait1()  { asm volatile("cp.async.wait_group 1;"); }
__device__ __forceinline__ void cp_wait0()  { asm volatile("cp.async.wait_group 0;"); }

// ---------------- pipelined tensor-core tf32 GEMM ----------------------------
// C[z] = Asel(z) @ Bsel(z) + bias (+resid).  BM=BN=128, BK=16, 256 threads.
// z&1 selects A (A0/A1) and resid (res0/res1); z>>1 selects B/bias (B0,bias0 / B1,bias1).
// KSPLIT: for k >= K/2, A switches to (A2 + (z&1)*a2Stride) with local k index.
// EPI_TF32: round output to tf32 before store.
template<int KSPLIT, int EPI_TF32>
__global__ __launch_bounds__(256)
void mma_gemm(
    const float* __restrict__ A0, const float* __restrict__ A1,
    const float* __restrict__ A2, long a2Stride,
    const float* __restrict__ B0, const float* __restrict__ B1,
    const float* __restrict__ bias0, const float* __restrict__ bias1,
    const float* __restrict__ res0, const float* __restrict__ res1,
    float* __restrict__ Cb, long cStride,
    int M, int N, int K, int lda, int ldb, int ldc, int ldr)
{
    constexpr int ASTR = 20;    // A smem row stride (floats)
    constexpr int BSTR = 136;   // B smem row stride (floats)
    __shared__ float As[2][128][ASTR];
    __shared__ float Bs[2][16][BSTR];

    const int z = blockIdx.z;
    const float* Aa  = (z & 1) ? A1 : A0;
    const float* Ab  = KSPLIT ? (A2 + (z & 1) * a2Stride) : nullptr;
    const float* B   = (z >> 1) ? B1 : B0;
    const float* bias= (z >> 1) ? bias1 : bias0;
    const float* res = (z & 1) ? res1 : res0;
    float* C = Cb + (long)z * cStride;

    const int tid  = threadIdx.x;
    const int warp = tid >> 5;
    const int lane = tid & 31;
    const int qr = lane >> 2, qc = lane & 3;
    const int rowBase = blockIdx.y * 128;
    const int colBase = blockIdx.x * 128;
    const int wm0 = (warp >> 1) * 32;   // 4 warp-rows (WM=32)
    const int wn0 = (warp & 1) * 64;    // 2 warp-cols (WN=64)

    float acc[2][8][4];
    #pragma unroll
    for (int i = 0; i < 2; i++)
        #pragma unroll
        for (int j = 0; j < 8; j++)
            #pragma unroll
            for (int r = 0; r < 4; r++) acc[i][j][r] = 0.f;

    const int KT = K / 16;
    const int Khalf = K / 2;

    // tile loader
    auto loadTile = [&](int st, int kt) {
        int k0 = kt * 16;
        const float* Ac; int kb;
        if (KSPLIT && k0 >= Khalf) { Ac = Ab; kb = k0 - Khalf; }
        else                       { Ac = Aa; kb = k0; }
        #pragma unroll
        for (int i = tid; i < 512; i += 256) {
            int m = i >> 2, kg = i & 3;
            cpa16(&As[st][m][kg * 4], Ac + (long)(rowBase + m) * lda + kb + kg * 4);
        }
        #pragma unroll
        for (int i = tid; i < 512; i += 256) {
            int r = i >> 5, c4 = (i & 31) * 4;
            cpa16(&Bs[st][r][c4], B + (long)(k0 + r) * ldb + colBase + c4);
        }
    };

    loadTile(0, 0);
    cp_commit();

    for (int kt = 0; kt < KT; kt++) {
        int st = kt & 1;
        if (kt + 1 < KT) { loadTile(st ^ 1, kt + 1); cp_commit(); cp_wait1(); }
        else             { cp_wait0(); }
        __syncthreads();

        #pragma unroll
        for (int ks = 0; ks < 16; ks += 8) {
            uint32_t af[2][4];
            #pragma unroll
            for (int mt = 0; mt < 2; mt++) {
                int mrr = wm0 + mt * 16;
                af[mt][0] = tf32u(As[st][mrr + qr    ][ks + qc]);
                af[mt][1] = tf32u(As[st][mrr + qr + 8][ks + qc]);
                af[mt][2] = tf32u(As[st][mrr + qr    ][ks + qc + 4]);
                af[mt][3] = tf32u(As[st][mrr + qr + 8][ks + qc + 4]);
            }
            uint32_t bf[8][2];
            #pragma unroll
            for (int nt = 0; nt < 8; nt++) {
                int nr = wn0 + nt * 8;
                bf[nt][0] = tf32u(Bs[st][ks + qc    ][nr + qr]);
                bf[nt][1] = tf32u(Bs[st][ks + qc + 4][nr + qr]);
            }
            #pragma unroll
            for (int mt = 0; mt < 2; mt++)
                #pragma unroll
                for (int nt = 0; nt < 8; nt++)
                    mma_tf32(acc[mt][nt], af[mt], bf[nt]);
        }
        __syncthreads();
    }

    #pragma unroll
    for (int mt = 0; mt < 2; mt++) {
        #pragma unroll
        for (int nt = 0; nt < 8; nt++) {
            int gm = rowBase + wm0 + mt * 16 + qr;
            int gn = colBase + wn0 + nt * 8 + qc * 2;
            float b0 = bias ? bias[gn] : 0.f;
            float b1 = bias ? bias[gn + 1] : 0.f;
            float v0 = acc[mt][nt][0] + b0;
            float v1 = acc[mt][nt][1] + b1;
            float v2 = acc[mt][nt][2] + b0;
            float v3 = acc[mt][nt][3] + b1;
            if (res) {
                const float2 r0 = *(const float2*)(res + (long)gm * ldr + gn);
                const float2 r1 = *(const float2*)(res + (long)(gm + 8) * ldr + gn);
                v0 += r0.x; v1 += r0.y; v2 += r1.x; v3 += r1.y;
            }
            if (EPI_TF32) {
                v0 = tf32r(v0); v1 = tf32r(v1); v2 = tf32r(v2); v3 = tf32r(v3);
            }
            *(float2*)(C + (long)gm * ldc + gn)       = make_float2(v0, v1);
            *(float2*)(C + (long)(gm + 8) * ldc + gn) = make_float2(v2, v3);
        }
    }
}

// ---------------- fused flash cross-attention (pipelined) --------------------
// grid (SEQ/64, BH, 2). z=0: O(m0)=softmax(qk0 qk1^T)v1 ; z=1: m1=softmax(qk1 qk0^T)v0
#define KSTR 68
#define VSTR 72
#define FL_P   0
#define FL_K0  4352
#define FL_V0  13056
#define FL_SMEM ((13056 + 2*4608) * 4)   // 89088 bytes

__global__ __launch_bounds__(128)
void flash_kernel(const float* __restrict__ qkv, float* __restrict__ mOut)
{
    extern __shared__ float sm[];
    const int z = blockIdx.z;
    const float* Qg = qkv + (long)z * SZ;
    const float* Kg = qkv + (long)(1 - z) * SZ;
    const float* Vg = qkv + (long)(3 - z) * SZ;
    float*       Og = mOut + (long)z * SZ;

    float (*Ps)[KSTR] = (float(*)[KSTR])(sm + FL_P);

    const long base = (long)(blockIdx.y >> 2) * SEQ * EMBED + (blockIdx.y & 3) * HDIM;
    const float* Qp = Qg + base + (long)blockIdx.x * 64 * EMBED;
    const float* K0 = Kg + base;
    const float* V0 = Vg + base;
    float*       Op = Og + base + (long)blockIdx.x * 64 * EMBED;

    const int tid  = threadIdx.x;
    const int warp = tid >> 5;
    const int lane = tid & 31;
    const int qr = lane >> 2, qc = lane & 3;
    const int mr = warp * 16;

    auto loadKV = [&](int st, int kb) {
        float* Ks = sm + FL_K0 + st * 4352;
        float* Vs = sm + FL_V0 + st * 4608;
        const float* Kp = K0 + (long)kb * 64 * EMBED;
        const float* Vp = V0 + (long)kb * 64 * EMBED;
        #pragma unroll
        for (int i = tid; i < 64 * 16; i += 128) {
            int r = i >> 4, c4 = (i & 15) * 4;
            cpa16(Ks + r * KSTR + c4, Kp + (long)r * EMBED + c4);
            cpa16(Vs + r * VSTR + c4, Vp + (long)r * EMBED + c4);
        }
    };

    // prefetch first K/V tile, then stage Q (overlap)
    loadKV(0, 0);
    cp_commit();

    #pragma unroll
    for (int i = tid; i < 64 * 16; i += 128) {
        int r = i >> 4, c4 = (i & 15) * 4;
        *(float4*)&Ps[r][c4] = *(const float4*)(Qp + (long)r * EMBED + c4);
    }
    __syncthreads();
    uint32_t qf[8][4];
    #pragma unroll
    for (int ks = 0; ks < 8; ks++) {
        qf[ks][0] = __float_as_uint(Ps[mr+qr  ][ks*8+qc  ]);
        qf[ks][1] = __float_as_uint(Ps[mr+qr+8][ks*8+qc  ]);
        qf[ks][2] = __float_as_uint(Ps[mr+qr  ][ks*8+qc+4]);
        qf[ks][3] = __float_as_uint(Ps[mr+qr+8][ks*8+qc+4]);
    }
    __syncthreads();   // all warps done with Q staging; Ps becomes warp-private P

    float oacc[8][4];
    #pragma unroll
    for (int nt = 0; nt < 8; nt++)
        #pragma unroll
        for (int j = 0; j < 4; j++) oacc[nt][j] = 0.f;
    float mrow0 = -1e30f, mrow1 = -1e30f, lrow0 = 0.f, lrow1 = 0.f;

    for (int kb = 0; kb < SEQ / 64; kb++) {
        int st = kb & 1;
        if (kb + 1 < SEQ / 64) { loadKV(st ^ 1, kb + 1); cp_commit(); cp_wait1(); }
        else                   { cp_wait0(); }
        __syncthreads();

        const float* Ks = sm + FL_K0 + st * 4352;
        const float* Vs = sm + FL_V0 + st * 4608;

        // ---- S = Q K^T ----
        float s[8][4];
        #pragma unroll
        for (int nt = 0; nt < 8; nt++)
            #pragma unroll
            for (int j = 0; j < 4; j++) s[nt][j] = 0.f;
        #pragma unroll
        for (int ks = 0; ks < 8; ks++) {
            #pragma unroll
            for (int nt = 0; nt < 8; nt++) {
                uint32_t bb[2] = {
                    __float_as_uint(Ks[(nt*8+qr)*KSTR + ks*8+qc    ]),
                    __float_as_uint(Ks[(nt*8+qr)*KSTR + ks*8+qc + 4]) };
                mma_tf32(s[nt], qf[ks], bb);
            }
        }

        // ---- online softmax ----
        float mx0 = -1e30f, mx1 = -1e30f;
        #pragma unroll
        for (int nt = 0; nt < 8; nt++) {
            s[nt][0] *= 0.125f; s[nt][1] *= 0.125f;
            s[nt][2] *= 0.125f; s[nt][3] *= 0.125f;
            mx0 = fmaxf(mx0, fmaxf(s[nt][0], s[nt][1]));
            mx1 = fmaxf(mx1, fmaxf(s[nt][2], s[nt][3]));
        }
        mx0 = fmaxf(mx0, __shfl_xor_sync(0xffffffffu, mx0, 1));
        mx0 = fmaxf(mx0, __shfl_xor_sync(0xffffffffu, mx0, 2));
        mx1 = fmaxf(mx1, __shfl_xor_sync(0xffffffffu, mx1, 1));
        mx1 = fmaxf(mx1, __shfl_xor_sync(0xffffffffu, mx1, 2));
        float mn0 = fmaxf(mrow0, mx0), mn1 = fmaxf(mrow1, mx1);
        float a0 = __expf(mrow0 - mn0), a1 = __expf(mrow1 - mn1);
        float sum0 = 0.f, sum1 = 0.f;
        #pragma unroll
        for (int nt = 0; nt < 8; nt++) {
            s[nt][0] = __expf(s[nt][0] - mn0); sum0 += s[nt][0];
            s[nt][1] = __expf(s[nt][1] - mn0); sum0 += s[nt][1];
            s[nt][2] = __expf(s[nt][2] - mn1); sum1 += s[nt][2];
            s[nt][3] = __expf(s[nt][3] - mn1); sum1 += s[nt][3];
        }
        sum0 += __shfl_xor_sync(0xffffffffu, sum0, 1);
        sum0 += __shfl_xor_sync(0xffffffffu, sum0, 2);
        sum1 += __shfl_xor_sync(0xffffffffu, sum1, 1);
        sum1 += __shfl_xor_sync(0xffffffffu, sum1, 2);
        lrow0 = lrow0 * a0 + sum0;  lrow1 = lrow1 * a1 + sum1;
        mrow0 = mn0;                mrow1 = mn1;
        #pragma unroll
        for (int nt = 0; nt < 8; nt++) {
            oacc[nt][0] *= a0; oacc[nt][1] *= a0;
            oacc[nt][2] *= a1; oacc[nt][3] *= a1;
        }

        // ---- P -> smem (warp-private rows) ; O += P V ----
        #pragma unroll
        for (int nt = 0; nt < 8; nt++) {
            Ps[mr+qr  ][nt*8+qc*2  ] = tf32r(s[nt][0]);
            Ps[mr+qr  ][nt*8+qc*2+1] = tf32r(s[nt][1]);
            Ps[mr+qr+8][nt*8+qc*2  ] = tf32r(s[nt][2]);
            Ps[mr+qr+8][nt*8+qc*2+1] = tf32r(s[nt][3]);
        }
        __syncwarp();
        #pragma unroll
        for (int ks = 0; ks < 8; ks++) {
            uint32_t af[4] = {
                __float_as_uint(Ps[mr+qr  ][ks*8+qc  ]),
                __float_as_uint(Ps[mr+qr+8][ks*8+qc  ]),
                __float_as_uint(Ps[mr+qr  ][ks*8+qc+4]),
                __float_as_uint(Ps[mr+qr+8][ks*8+qc+4]) };
            #pragma unroll
            for (int nt = 0; nt < 8; nt++) {
                uint32_t bb[2] = {
                    __float_as_uint(Vs[(ks*8+qc  )*VSTR + nt*8+qr]),
                    __float_as_uint(Vs[(ks*8+qc+4)*VSTR + nt*8+qr]) };
                mma_tf32(oacc[nt], af, bb);
            }
        }
        __syncthreads();   // protect K/V stage before reuse
    }

    float inv0 = 1.f / lrow0, inv1 = 1.f / lrow1;
    #pragma unroll
    for (int nt = 0; nt < 8; nt++) {
        int col = nt * 8 + qc * 2;
        *(float2*)(Op + (long)(mr+qr  ) * EMBED + col) =
            make_float2(oacc[nt][0] * inv0, oacc[nt][1] * inv0);
        *(float2*)(Op + (long)(mr+qr+8) * EMBED + col) =
            make_float2(oacc[nt][2] * inv1, oacc[nt][3] * inv1);
    }
}

// ---------------- LayerNorm(512) + exact GELU, in place ---------------------
__global__ void ln_gelu_kernel(float* __restrict__ y,
                               const float* __restrict__ sc,
                               const float* __restrict__ bi)
{
    float* row = y + (long)blockIdx.x * (2 * EMBED);
    int t = threadIdx.x;
    float a = row[t], b = row[t + 256];

    __shared__ float red[256];
    red[t] = a + b; __syncthreads();
    for (int s = 128; s > 0; s >>= 1) {
        if (t < s) red[t] += red[t + s];
        __syncthreads();
    }
    float mean = red[0] * (1.f / 512.f);
    __syncthreads();

    float da = a - mean, db = b - mean;
    red[t] = da * da + db * db; __syncthreads();
    for (int s = 128; s > 0; s >>= 1) {
        if (t < s) red[t] += red[t + s];
        __syncthreads();
    }
    float inv = rsqrtf(red[0] * (1.f / 512.f) + 1e-5f);

    float g1 = da * inv * sc[t]       + bi[t];
    float g2 = db * inv * sc[t + 256] + bi[t + 256];
    row[t]       = 0.5f * g1 * (1.f + erff(g1 * 0.70710678118654752f));
    row[t + 256] = 0.5f * g2 * (1.f + erff(g2 * 0.70710678118654752f));
}

// ---------------- host side --------------------------------------------------
extern "C" void kernel_launch(void* const* d_in, const int* in_sizes, int n_in,
                              void* d_out, int out_size)
{
    const float* x0       = (const float*)d_in[0];
    const float* x1       = (const float*)d_in[1];
    const float* Wqk      = (const float*)d_in[2];
    const float* bqk      = (const float*)d_in[3];
    const float* Wv       = (const float*)d_in[4];
    const float* bv       = (const float*)d_in[5];
    const float* Wout     = (const float*)d_in[6];
    const float* bout     = (const float*)d_in[7];
    const float* W0       = (const float*)d_in[8];
    const float* b0       = (const float*)d_in[9];
    const float* ln_scale = (const float*)d_in[10];
    const float* ln_bias  = (const float*)d_in[11];
    const float* W3       = (const float*)d_in[12];
    const float* b3       = (const float*)d_in[13];
    float* out = (float*)d_out;

    float *qkv, *m, *mo, *y;
    cudaGetSymbolAddress((void**)&qkv, g_qkv);
    cudaGetSymbolAddress((void**)&m,   g_m);
    cudaGetSymbolAddress((void**)&mo,  g_mo);
    cudaGetSymbolAddress((void**)&y,   g_y);

    cudaFuncSetAttribute(flash_kernel,
                         cudaFuncAttributeMaxDynamicSharedMemorySize, FL_SMEM);

    // 1) projections: z in {0:x0@Wqk, 1:x1@Wqk, 2:x0@Wv, 3:x1@Wv} -> g_qkv[z]
    //    epilogue rounds to tf32 so flash can skip conversions.
    mma_gemm<0,1><<<dim3(2, 64, 4), 256>>>(
        x0, x1, nullptr, 0, Wqk, Wv, bqk, bv, nullptr, nullptr,
        qkv, SZ, ROWS, EMBED, EMBED, EMBED, EMBED, EMBED, 0);

    // 2) flash cross-attention, both directions in one launch
    flash_kernel<<<dim3(SEQ/64, BH, 2), 128, FL_SMEM>>>(qkv, m);

    // 3) mo_z = m_z @ Wout + bout
    mma_gemm<0,0><<<dim3(2, 64, 2), 256>>>(
        m, m + SZ, nullptr, 0, Wout, Wout, bout, bout, nullptr, nullptr,
        mo, SZ, ROWS, EMBED, EMBED, EMBED, EMBED, EMBED, 0);

    // 4) y_z = [x_z | mo_z] @ W0 + b0   (split-A over K=512)
    mma_gemm<1,0><<<dim3(4, 64, 2), 256>>>(
        x0, x1, mo, SZ, W0, W0, b0, b0, nullptr, nullptr,
        y, (long)ROWS * 512, ROWS, 512, 512, EMBED, 512, 512, 0);

    // 5) LayerNorm + GELU in place (both streams)
    ln_gelu_kernel<<<2 * ROWS, 256>>>(y, ln_scale, ln_bias);

    // 6) out_z = x_z + y_z @ W3 + b3
    mma_gemm<0,0><<<dim3(2, 64, 2), 256>>>(
        y, y + (long)ROWS * 512, nullptr, 0, W3, W3, b3, b3, x0, x1,
        out, SZ, ROWS, EMBED, 512, 512, EMBED, EMBED, EMBED);
}